// round 2
// baseline (speedup 1.0000x reference)
#include <cuda_runtime.h>

#define B_   8
#define T_   2048
#define D_   1024
#define KQ_  128
#define TOPK 8
#define BT_  (B_ * T_)

#define GATH_N ((size_t)BT_ * TOPK * D_)   // 134217728
#define IDX_N  ((size_t)BT_ * TOPK)        // 131072

// Scratch (allocation-free rule: __device__ globals)
__device__ float g_q[BT_ * KQ_];
__device__ float g_k[BT_ * KQ_];
__device__ int   g_idx[BT_ * TOPK];

// ---------------------------------------------------------------------------
// f32x2 helpers (Blackwell packed fp32: 2 FMAs per issue slot)
// ---------------------------------------------------------------------------
__device__ __forceinline__ void ffma2(unsigned long long& d,
                                      unsigned long long a,
                                      unsigned long long b) {
    asm("fma.rn.f32x2 %0, %1, %2, %0;" : "+l"(d) : "l"(a), "l"(b));
}
__device__ __forceinline__ unsigned long long dup2(float v) {
    unsigned long long r;
    asm("mov.b64 %0, {%1, %1};" : "=l"(r) : "f"(v));
    return r;
}
__device__ __forceinline__ float2 unpk(unsigned long long u) {
    float2 f;
    asm("mov.b64 {%0, %1}, %2;" : "=f"(f.x), "=f"(f.y) : "l"(u));
    return f;
}

// ---------------------------------------------------------------------------
// Kernel A: fused Q/K projection.  GEMM M=16384, N=256 (q||k), K=1024.
// Tile BM=64, BN=256, BK=32; 256 threads; per-thread 8x8 via FFMA2:
// accumulator pairs over adjacent rows (natural LDS pairs), B duplicated.
// ---------------------------------------------------------------------------
__global__ __launch_bounds__(256, 2) void proj_kernel(
    const float* __restrict__ x,
    const float* __restrict__ Wq, const float* __restrict__ bq,
    const float* __restrict__ Wk, const float* __restrict__ bk)
{
    __shared__ float As[32][68];    // x tile, transposed: As[d][m]
    __shared__ float Bs[32][260];   // W tile, transposed: Bs[d][n]

    const int tid = threadIdx.x;
    const int m0  = blockIdx.x * 64;
    const int ty  = tid >> 5;   // 0..7  -> rows ty*8..ty*8+7
    const int tx  = tid & 31;   // 0..31 -> cols tx*8..tx*8+7

    unsigned long long acc[4][8];   // [row-pair][col]
#pragma unroll
    for (int i = 0; i < 4; i++)
#pragma unroll
        for (int j = 0; j < 8; j++) acc[i][j] = 0ULL;

    for (int k0 = 0; k0 < D_; k0 += 32) {
#pragma unroll
        for (int l = 0; l < 2; l++) {
            int e  = tid + l * 256;
            int r  = e >> 3;
            int c4 = e & 7;
            float4 v = *reinterpret_cast<const float4*>(
                &x[(size_t)(m0 + r) * D_ + k0 + c4 * 4]);
            As[c4 * 4 + 0][r] = v.x;
            As[c4 * 4 + 1][r] = v.y;
            As[c4 * 4 + 2][r] = v.z;
            As[c4 * 4 + 3][r] = v.w;
        }
#pragma unroll
        for (int l = 0; l < 8; l++) {
            int e  = tid + l * 256;
            int n  = e >> 3;
            int c4 = e & 7;
            const float* Wsrc = (n < 128) ? &Wq[(size_t)n * D_]
                                          : &Wk[(size_t)(n - 128) * D_];
            float4 v = *reinterpret_cast<const float4*>(&Wsrc[k0 + c4 * 4]);
            Bs[c4 * 4 + 0][n] = v.x;
            Bs[c4 * 4 + 1][n] = v.y;
            Bs[c4 * 4 + 2][n] = v.z;
            Bs[c4 * 4 + 3][n] = v.w;
        }
        __syncthreads();

#pragma unroll 4
        for (int d = 0; d < 32; d++) {
            ulonglong2 a01 = *reinterpret_cast<const ulonglong2*>(&As[d][ty * 8]);
            ulonglong2 a23 = *reinterpret_cast<const ulonglong2*>(&As[d][ty * 8 + 4]);
            float4 bv0 = *reinterpret_cast<const float4*>(&Bs[d][tx * 8]);
            float4 bv1 = *reinterpret_cast<const float4*>(&Bs[d][tx * 8 + 4]);
            unsigned long long ap[4] = {a01.x, a01.y, a23.x, a23.y};
            unsigned long long bd[8] = {dup2(bv0.x), dup2(bv0.y), dup2(bv0.z), dup2(bv0.w),
                                        dup2(bv1.x), dup2(bv1.y), dup2(bv1.z), dup2(bv1.w)};
#pragma unroll
            for (int i = 0; i < 4; i++)
#pragma unroll
                for (int j = 0; j < 8; j++) ffma2(acc[i][j], ap[i], bd[j]);
        }
        __syncthreads();
    }

    // epilogue: cols [0,128) -> q, [128,256) -> k
    float* dst;
    const float* bias;
    int n0;
    if (tx < 16) { dst = g_q; bias = bq; n0 = tx * 8; }
    else         { dst = g_k; bias = bk; n0 = (tx - 16) * 8; }
    float bb[8];
#pragma unroll
    for (int j = 0; j < 8; j++) bb[j] = bias[n0 + j];

#pragma unroll
    for (int ip = 0; ip < 4; ip++) {
        float2 c[8];
#pragma unroll
        for (int j = 0; j < 8; j++) c[j] = unpk(acc[ip][j]);
#pragma unroll
        for (int e = 0; e < 2; e++) {
            int m = m0 + ty * 8 + ip * 2 + e;
            float v[8];
#pragma unroll
            for (int j = 0; j < 8; j++) v[j] = (e ? c[j].y : c[j].x) + bb[j];
            *reinterpret_cast<float4*>(&dst[(size_t)m * KQ_ + n0]) =
                make_float4(v[0], v[1], v[2], v[3]);
            *reinterpret_cast<float4*>(&dst[(size_t)m * KQ_ + n0 + 4]) =
                make_float4(v[4], v[5], v[6], v[7]);
        }
    }
}

// ---------------------------------------------------------------------------
// Kernel B: fused sim = q @ k^T + per-row top-8, sim never hits global.
// Block: 64 t-rows x 64 s-cols per tile, 32 s-tiles; 128 threads; 3 CTAs/SM
// so the serial scan phase overlaps other CTAs' MMA. FFMA2 MMA.
// ---------------------------------------------------------------------------
__device__ __forceinline__ void tk_insert(float v, int idx,
                                          float* topv, int* topi) {
    if (v > topv[TOPK - 1]) {
        topv[TOPK - 1] = v;
        topi[TOPK - 1] = idx;
#pragma unroll
        for (int p = TOPK - 1; p > 0; p--) {
            if (topv[p] > topv[p - 1]) {   // strict: keeps lower index first on ties
                float tv = topv[p]; topv[p] = topv[p - 1]; topv[p - 1] = tv;
                int   ti = topi[p]; topi[p] = topi[p - 1]; topi[p - 1] = ti;
            }
        }
    }
}

__global__ __launch_bounds__(128, 3) void sim_topk_kernel(float* __restrict__ out)
{
    extern __shared__ float smem[];
    float* Qs = smem;               // [128 d][68] : Qs[d*68 + t]
    float* Ks = smem + 128 * 68;    // [128 d][68] : Ks[d*68 + s]; reused as sim[t*68+s]

    const int tid = threadIdx.x;
    const int b   = blockIdx.y;
    const int t0  = blockIdx.x * 64;
    const int ty  = tid >> 4;   // 0..7  -> rows ty*8
    const int tx  = tid & 15;   // 0..15 -> cols tx*4

    // load Q tile once: 64 rows x 128 d, transposed
    {
        const float* qbase = &g_q[((size_t)b * T_ + t0) * KQ_];
#pragma unroll
        for (int l = 0; l < 16; l++) {
            int e  = tid + l * 128;   // 0..2047
            int r  = e >> 5;          // t row 0..63
            int c4 = e & 31;
            float4 v = *reinterpret_cast<const float4*>(&qbase[r * KQ_ + c4 * 4]);
            Qs[(c4 * 4 + 0) * 68 + r] = v.x;
            Qs[(c4 * 4 + 1) * 68 + r] = v.y;
            Qs[(c4 * 4 + 2) * 68 + r] = v.z;
            Qs[(c4 * 4 + 3) * 68 + r] = v.w;
        }
    }

    float topv[TOPK];
    int   topi[TOPK];
#pragma unroll
    for (int j = 0; j < TOPK; j++) { topv[j] = -3.402823466e38f; topi[j] = 0; }

    for (int st = 0; st < 32; st++) {
        __syncthreads();  // Q ready (st=0) / prior scan done before Ks overwrite

        {   // load K tile: 64 s-rows x 128 d, transposed
            const float* kbase = &g_k[((size_t)b * T_ + st * 64) * KQ_];
#pragma unroll
            for (int l = 0; l < 16; l++) {
                int e  = tid + l * 128;
                int r  = e >> 5;
                int c4 = e & 31;
                float4 v = *reinterpret_cast<const float4*>(&kbase[r * KQ_ + c4 * 4]);
                Ks[(c4 * 4 + 0) * 68 + r] = v.x;
                Ks[(c4 * 4 + 1) * 68 + r] = v.y;
                Ks[(c4 * 4 + 2) * 68 + r] = v.z;
                Ks[(c4 * 4 + 3) * 68 + r] = v.w;
            }
        }
        __syncthreads();

        unsigned long long acc[4][4];
#pragma unroll
        for (int i = 0; i < 4; i++)
#pragma unroll
            for (int j = 0; j < 4; j++) acc[i][j] = 0ULL;

#pragma unroll 8
        for (int d = 0; d < 128; d++) {
            ulonglong2 a01 = *reinterpret_cast<const ulonglong2*>(&Qs[d * 68 + ty * 8]);
            ulonglong2 a23 = *reinterpret_cast<const ulonglong2*>(&Qs[d * 68 + ty * 8 + 4]);
            float4 bv = *reinterpret_cast<const float4*>(&Ks[d * 68 + tx * 4]);
            unsigned long long ap[4] = {a01.x, a01.y, a23.x, a23.y};
            unsigned long long b0 = dup2(bv.x), b1 = dup2(bv.y),
                               b2 = dup2(bv.z), b3 = dup2(bv.w);
#pragma unroll
            for (int i = 0; i < 4; i++) {
                ffma2(acc[i][0], ap[i], b0);
                ffma2(acc[i][1], ap[i], b1);
                ffma2(acc[i][2], ap[i], b2);
                ffma2(acc[i][3], ap[i], b3);
            }
        }
        __syncthreads();  // all Ks reads done -> safe to overwrite with sims

        // stage sims: sim[t][s] into Ks region, stride 68
#pragma unroll
        for (int ip = 0; ip < 4; ip++) {
            float2 c0 = unpk(acc[ip][0]), c1 = unpk(acc[ip][1]);
            float2 c2 = unpk(acc[ip][2]), c3 = unpk(acc[ip][3]);
            int r0 = ty * 8 + ip * 2;
            *reinterpret_cast<float4*>(&Ks[r0 * 68 + tx * 4]) =
                make_float4(c0.x, c1.x, c2.x, c3.x);
            *reinterpret_cast<float4*>(&Ks[(r0 + 1) * 68 + tx * 4]) =
                make_float4(c0.y, c1.y, c2.y, c3.y);
        }
        __syncthreads();

        // per-row top-8 fold: thread r owns t-row r, scans 64 values (16 float4)
        if (tid < 64) {
            const float4* srow = reinterpret_cast<const float4*>(&Ks[tid * 68]);
            int sbase = st * 64;
#pragma unroll 4
            for (int i = 0; i < 16; i++) {
                float4 v = srow[i];
                float mx = fmaxf(fmaxf(v.x, v.y), fmaxf(v.z, v.w));
                if (mx > topv[TOPK - 1]) {   // rare path
                    tk_insert(v.x, sbase + i * 4 + 0, topv, topi);
                    tk_insert(v.y, sbase + i * 4 + 1, topv, topi);
                    tk_insert(v.z, sbase + i * 4 + 2, topv, topi);
                    tk_insert(v.w, sbase + i * 4 + 3, topv, topi);
                }
            }
        }
    }

    if (tid < 64) {
        const float scale = 0.08838834764831843f;  // 1/sqrt(128)
        size_t row = (size_t)b * T_ + (t0 + tid);
        float* out_idx = out + GATH_N;
        float* out_sim = out + GATH_N + IDX_N;
#pragma unroll
        for (int j = 0; j < TOPK; j++) {
            g_idx[row * TOPK + j]   = topi[j];
            out_idx[row * TOPK + j] = (float)topi[j];
            out_sim[row * TOPK + j] = topv[j] * scale;
        }
    }
}

// ---------------------------------------------------------------------------
// Kernel C: gather routed tokens. One block per (b,t,j) output row.
// x (64MB) is L2-resident; this is a pure 512MB store-bandwidth kernel.
// ---------------------------------------------------------------------------
__global__ __launch_bounds__(256) void gather_kernel(
    const float* __restrict__ x, float* __restrict__ out)
{
    int r = blockIdx.x;                    // 0 .. B*T*8-1
    int b = r >> 14;                       // r / (T_*TOPK)
    int src_t = g_idx[r];
    const float4* src = reinterpret_cast<const float4*>(
        &x[((size_t)b * T_ + src_t) * D_]);
    float4* dst = reinterpret_cast<float4*>(&out[(size_t)r * D_]);
    dst[threadIdx.x] = src[threadIdx.x];
}

// ---------------------------------------------------------------------------
extern "C" void kernel_launch(void* const* d_in, const int* in_sizes, int n_in,
                              void* d_out, int out_size)
{
    const float* x  = (const float*)d_in[0];
    const float* Wq = (const float*)d_in[1];
    const float* bq = (const float*)d_in[2];
    const float* Wk = (const float*)d_in[3];
    const float* bk = (const float*)d_in[4];
    float* out = (float*)d_out;

    proj_kernel<<<BT_ / 64, 256>>>(x, Wq, bq, Wk, bk);

    int smemB = 2 * 128 * 68 * (int)sizeof(float);   // 69632 B
    cudaFuncSetAttribute(sim_topk_kernel,
                         cudaFuncAttributeMaxDynamicSharedMemorySize, smemB);
    dim3 gridB(T_ / 64, B_);
    sim_topk_kernel<<<gridB, 128, smemB>>>(out);

    gather_kernel<<<BT_ * TOPK, 256>>>(x, out);
}